// round 15
// baseline (speedup 1.0000x reference)
#include <cuda_runtime.h>
#include <cuda_fp16.h>
#include <cstdint>

// ---------------- static device scratch (no allocations allowed) ----------------
__device__ __half g_T3h[4096 * 512];    // 4 MB : in-contracted activations (fp16)
__device__ float  g_U  [4096 * 512];    // 8 MB : core-contracted activations (fp32)
__device__ __half g_coreH[512 * 512];   // 0.5 MB : core pre-converted to fp16

__device__ __forceinline__ uint32_t smem_u32(const void* p) {
    uint32_t a;
    asm("{ .reg .u64 t; cvta.to.shared.u64 t, %1; cvt.u32.u64 %0, t; }" : "=r"(a) : "l"(p));
    return a;
}
__device__ __forceinline__ uint32_t pack_h2(float a, float b) {
    __half2 h = __floats2half2_rn(a, b);
    return *(uint32_t*)&h;
}
// ---- packed fp32 (Blackwell f32x2) ----
__device__ __forceinline__ uint64_t pk2(float lo, float hi) {
    uint64_t r; asm("mov.b64 %0, {%1, %2};" : "=l"(r) : "f"(lo), "f"(hi)); return r;
}
__device__ __forceinline__ void upk2(float& lo, float& hi, uint64_t v) {
    asm("mov.b64 {%0, %1}, %2;" : "=f"(lo), "=f"(hi) : "l"(v));
}
__device__ __forceinline__ void ffma2(uint64_t& d, uint64_t a, uint64_t b) {
    asm("fma.rn.f32x2 %0, %1, %2, %0;" : "+l"(d) : "l"(a), "l"(b));
}
#define CP_ASYNC16(dst, src) \
    asm volatile("cp.async.cg.shared.global [%0], [%1], 16;" :: "r"(dst), "l"(src) : "memory")
#define CP_COMMIT() asm volatile("cp.async.commit_group;" ::: "memory")
#define CP_WAIT(n)  asm volatile("cp.async.wait_group %0;" :: "n"(n) : "memory")

// ---------------- K1: stage A — 2 warps/sample, t2 overlays t1, FFMA2 math ----------------
static constexpr int T1L = 272;
static constexpr int SAMP = 8 * T1L;                        // 2176 floats / sample
static constexpr int SMEM_A = (2 * SAMP + 384) * 4;         // 18944 B

__global__ __launch_bounds__(128, 8) void k_stageA(const float* __restrict__ x,
                                                   const float* __restrict__ f3,
                                                   const float* __restrict__ f4,
                                                   const float* __restrict__ f5,
                                                   const float* __restrict__ core) {
    extern __shared__ float sm[];
    float* f3s = sm + 2 * SAMP;
    float* f4s = f3s + 128;
    float* f5s = f4s + 128;

    int t = threadIdx.x, wid = t >> 5, lane = t & 31;
    int sid = wid >> 1, half = wid & 1;

    if (t < 32) {
        int i = (blockIdx.x * 32 + t) * 4;
        float4 v = *(const float4*)(core + i);
        uint2 o = make_uint2(pack_h2(v.x, v.y), pack_h2(v.z, v.w));
        *(uint2*)(g_coreH + i) = o;
    }
    f3s[t] = f3[t]; f4s[t] = f4[t]; f5s[t] = f5[t];
    __syncthreads();

    float* t1s = sm + sid * SAMP;
    long s = (long)blockIdx.x * 2 + sid;
    const float* xs = x + s * 4096 + half * 128 + 4 * lane;

    // ---- phase 1: acc2[q][lp] packs (l=2lp, 2lp+1) ----
    {
        uint64_t acc2[4][4];
#pragma unroll
        for (int q = 0; q < 4; q++)
#pragma unroll
            for (int lp = 0; lp < 4; lp++) acc2[q][lp] = 0ULL;
#pragma unroll 4
        for (int d = 0; d < 16; d++) {
            float4 xv = *(const float4*)(xs + d * 256);
            uint64_t xb[4] = { pk2(xv.x, xv.x), pk2(xv.y, xv.y),
                               pk2(xv.z, xv.z), pk2(xv.w, xv.w) };
            const uint64_t* fp = (const uint64_t*)(f3s + d * 8);
            uint64_t f0p = fp[0], f1p = fp[1], f2p = fp[2], f3p = fp[3];
#pragma unroll
            for (int q = 0; q < 4; q++) {
                ffma2(acc2[q][0], xb[q], f0p);
                ffma2(acc2[q][1], xb[q], f1p);
                ffma2(acc2[q][2], xb[q], f2p);
                ffma2(acc2[q][3], xb[q], f3p);
            }
        }
#pragma unroll
        for (int lp = 0; lp < 4; lp++) {
            float a0, b0, a1, b1, a2, b2, a3, b3;
            upk2(a0, b0, acc2[0][lp]); upk2(a1, b1, acc2[1][lp]);
            upk2(a2, b2, acc2[2][lp]); upk2(a3, b3, acc2[3][lp]);
            *(float4*)(t1s + (2 * lp) * T1L + half * 128 + 4 * lane) =
                make_float4(a0, a1, a2, a3);
            *(float4*)(t1s + (2 * lp + 1) * T1L + half * 128 + 4 * lane) =
                make_float4(b0, b1, b2, b3);
        }
    }
    __syncthreads();

    // ---- phase 2: acc2[z][mp] packs (m=2mp, 2mp+1); t2 overlays t1 ----
    {
        uint64_t acc2[2][4];
#pragma unroll
        for (int z = 0; z < 2; z++)
#pragma unroll
            for (int mp = 0; mp < 4; mp++) acc2[z][mp] = 0ULL;
#pragma unroll
        for (int e = 0; e < 16; e++) {
            uint64_t tb[2];
#pragma unroll
            for (int z = 0; z < 2; z++) {
                int p = half * 64 + 32 * z + lane, l = p >> 4, f = p & 15;
                float tv = t1s[l * T1L + e * 16 + f];
                tb[z] = pk2(tv, tv);
            }
            const uint64_t* fp = (const uint64_t*)(f4s + e * 8);
            uint64_t f0p = fp[0], f1p = fp[1], f2p = fp[2], f3p = fp[3];
#pragma unroll
            for (int z = 0; z < 2; z++) {
                ffma2(acc2[z][0], tb[z], f0p);
                ffma2(acc2[z][1], tb[z], f1p);
                ffma2(acc2[z][2], tb[z], f2p);
                ffma2(acc2[z][3], tb[z], f3p);
            }
        }
        __syncthreads();
#pragma unroll
        for (int z = 0; z < 2; z++) {
            int p = half * 64 + 32 * z + lane, l = p >> 4, f = p & 15;
#pragma unroll
            for (int mp = 0; mp < 4; mp++) {
                float lo, hi;
                upk2(lo, hi, acc2[z][mp]);
                t1s[l * 144 + (2 * mp) * 17 + f] = lo;
                t1s[l * 144 + (2 * mp + 1) * 17 + f] = hi;
            }
        }
    }
    __syncthreads();

    // ---- phase 3: acc2[np] packs (n=2np, 2np+1) -> fp16 directly ----
    {
        int lm = half * 32 + lane, l = lm >> 3, m = lm & 7;
        uint64_t acc2[4] = { 0ULL, 0ULL, 0ULL, 0ULL };
#pragma unroll
        for (int f = 0; f < 16; f++) {
            float tv = t1s[l * 144 + m * 17 + f];
            uint64_t tb = pk2(tv, tv);
            const uint64_t* fp = (const uint64_t*)(f5s + f * 8);
            ffma2(acc2[0], tb, fp[0]);
            ffma2(acc2[1], tb, fp[1]);
            ffma2(acc2[2], tb, fp[2]);
            ffma2(acc2[3], tb, fp[3]);
        }
        uint32_t o[4];
#pragma unroll
        for (int np = 0; np < 4; np++) {
            float lo, hi;
            upk2(lo, hi, acc2[np]);
            o[np] = pack_h2(lo, hi);
        }
        *(uint4*)(g_T3h + s * 512 + lm * 8) = make_uint4(o[0], o[1], o[2], o[3]);
    }
}

// ---------------- K2: stage B via mma.sync fp16 (m16n8k16), 512 threads, 3-stage ----------------
static constexpr int GS = 36;
static constexpr int OP_ST = 128 * GS;
static constexpr int GEMM_SMEM = 6 * OP_ST * 4;       // 110592 B

__global__ __launch_bounds__(512) void k_gemm_mma() {
    extern __shared__ float sm[];
    uint32_t sm_u = smem_u32(sm);

    int t = threadIdx.x;
    int lane = t & 31, wid = t >> 5;
    int warp_m = (wid & 3) * 32;
    int warp_n = (wid >> 2) * 32;
    long s0 = (long)blockIdx.x * 128;
    int n0 = blockIdx.y * 128;

    int rr[2], sg[2];
#pragma unroll
    for (int i = 0; i < 2; i++) {
        int ii = t + 512 * i;
        rr[i] = ii >> 3;
        sg[i] = ii & 7;
    }
    const __half* AGp[2]; const __half* BGp[2]; uint32_t Sd[2];
#pragma unroll
    for (int i = 0; i < 2; i++) {
        AGp[i] = g_T3h + (s0 + rr[i]) * 512 + sg[i] * 8;
        BGp[i] = g_coreH + (size_t)(n0 + rr[i]) * 512 + sg[i] * 8;
        Sd[i] = (uint32_t)((rr[i] * GS + sg[i] * 4) * 4);
    }

    float acc[2][4][4];
#pragma unroll
    for (int mt = 0; mt < 2; mt++)
#pragma unroll
        for (int nt = 0; nt < 4; nt++)
#pragma unroll
            for (int i = 0; i < 4; i++) acc[mt][nt][i] = 0.f;

    int fr = lane >> 2, fc = lane & 3;

#pragma unroll
    for (int pc = 0; pc < 2; pc++) {
        uint32_t Au = sm_u + (2 * pc) * OP_ST * 4;
        uint32_t Bu = sm_u + (2 * pc + 1) * OP_ST * 4;
#pragma unroll
        for (int i = 0; i < 2; i++) {
            CP_ASYNC16(Au + Sd[i], AGp[i] + pc * 64);
            CP_ASYNC16(Bu + Sd[i], BGp[i] + pc * 64);
        }
        CP_COMMIT();
    }

#pragma unroll 1
    for (int c = 0; c < 8; c++) {
        int p = c % 3;
        if (c == 7) { CP_WAIT(0); } else { CP_WAIT(1); }
        __syncthreads();

        const float* As = sm + (2 * p) * OP_ST;
        const float* Bs = sm + (2 * p + 1) * OP_ST;
#pragma unroll
        for (int ks = 0; ks < 4; ks++) {
            int k0 = ks * 8;
            uint32_t a[2][4], b[4][2];
#pragma unroll
            for (int mt = 0; mt < 2; mt++) {
                const float* ab = As + (warp_m + mt * 16 + fr) * GS + k0 + fc;
                a[mt][0] = __float_as_uint(ab[0]);
                a[mt][1] = __float_as_uint(ab[8 * GS]);
                a[mt][2] = __float_as_uint(ab[4]);
                a[mt][3] = __float_as_uint(ab[8 * GS + 4]);
            }
#pragma unroll
            for (int nt = 0; nt < 4; nt++) {
                const float* bb = Bs + (warp_n + nt * 8 + fr) * GS + k0 + fc;
                b[nt][0] = __float_as_uint(bb[0]);
                b[nt][1] = __float_as_uint(bb[4]);
            }
#pragma unroll
            for (int mt = 0; mt < 2; mt++)
#pragma unroll
                for (int nt = 0; nt < 4; nt++)
                    asm volatile(
                        "mma.sync.aligned.m16n8k16.row.col.f32.f16.f16.f32 "
                        "{%0,%1,%2,%3}, {%4,%5,%6,%7}, {%8,%9}, {%0,%1,%2,%3};"
                        : "+f"(acc[mt][nt][0]), "+f"(acc[mt][nt][1]),
                          "+f"(acc[mt][nt][2]), "+f"(acc[mt][nt][3])
                        : "r"(a[mt][0]), "r"(a[mt][1]), "r"(a[mt][2]), "r"(a[mt][3]),
                          "r"(b[nt][0]), "r"(b[nt][1]));
        }

        if (c + 2 < 8) {
            int pn = (c + 2) % 3;
            uint32_t Au = sm_u + (2 * pn) * OP_ST * 4;
            uint32_t Bu = sm_u + (2 * pn + 1) * OP_ST * 4;
            int off = (c + 2) * 64;
#pragma unroll
            for (int i = 0; i < 2; i++) {
                CP_ASYNC16(Au + Sd[i], AGp[i] + off);
                CP_ASYNC16(Bu + Sd[i], BGp[i] + off);
            }
            CP_COMMIT();
        }
    }

    int cp = (lane & 3) * 2;
#pragma unroll
    for (int mt = 0; mt < 2; mt++)
#pragma unroll
        for (int h = 0; h < 2; h++) {
            long m = s0 + warp_m + mt * 16 + fr + h * 8;
            float* dst = g_U + m * 512 + n0 + warp_n + cp;
#pragma unroll
            for (int nt = 0; nt < 4; nt++) {
                float2 v = make_float2(acc[mt][nt][h * 2], acc[mt][nt][h * 2 + 1]);
                *(float2*)(dst + nt * 8) = v;
            }
        }
}

// ---------------- K3: stage C (block version, transposed factors, FFMA2 math) ----------------
__global__ __launch_bounds__(256, 3) void k_stageC(const float* __restrict__ f0,
                                                   const float* __restrict__ f1,
                                                   const float* __restrict__ f2,
                                                   const float* __restrict__ bias,
                                                   float* __restrict__ y) {
    extern __shared__ float sm[];
    float* u1s = sm;                    // 4 * 1152
    float* u2s = sm + 4 * 1152;         // 4 * 2176
    float* f0t = u2s + 4 * 2176;        // f0t[i*16+a]
    float* f1t = f0t + 128;             // f1t[j*16+b]
    float* f2t = f1t + 128;             // f2t[k*16+c]

    int t = threadIdx.x;
    if (t < 128) {
        int rr = t >> 3, cc = t & 7;
        f0t[cc * 16 + rr] = f0[t];
        f1t[cc * 16 + rr] = f1[t];
        f2t[cc * 16 + rr] = f2[t];
    }
    __syncthreads();

    long s0 = (long)blockIdx.x * 4;

    // ---- phase 1: acc2[s][ap] packs (a4 = 2ap, 2ap+1) ----
    {
        int g = t >> 6, jk = t & 63;
        uint64_t acc2[4][2];
#pragma unroll
        for (int s = 0; s < 4; s++) { acc2[s][0] = 0ULL; acc2[s][1] = 0ULL; }
#pragma unroll
        for (int i = 0; i < 8; i++) {
            uint64_t ub[4];
#pragma unroll
            for (int s = 0; s < 4; s++) {
                float uv = g_U[(s0 + s) * 512 + i * 64 + jk];
                ub[s] = pk2(uv, uv);
            }
            const uint64_t* fp = (const uint64_t*)(f0t + i * 16 + g * 4);
            uint64_t f0p = fp[0], f1p = fp[1];
#pragma unroll
            for (int s = 0; s < 4; s++) {
                ffma2(acc2[s][0], ub[s], f0p);
                ffma2(acc2[s][1], ub[s], f1p);
            }
        }
#pragma unroll
        for (int s = 0; s < 4; s++)
#pragma unroll
            for (int ap = 0; ap < 2; ap++) {
                float lo, hi;
                upk2(lo, hi, acc2[s][ap]);
                u1s[s * 1152 + (g * 4 + 2 * ap) * 72 + jk] = lo;
                u1s[s * 1152 + (g * 4 + 2 * ap + 1) * 72 + jk] = hi;
            }
    }
    __syncthreads();

    // ---- phase 2: acc2[z][bp] packs (b = 2bp, 2bp+1) ----
    {
        int h = t >> 7, pair = t & 127;
        int a = pair >> 3, k = pair & 7;
        uint64_t acc2[2][8];
#pragma unroll
        for (int z = 0; z < 2; z++)
#pragma unroll
            for (int bp = 0; bp < 8; bp++) acc2[z][bp] = 0ULL;
#pragma unroll
        for (int j = 0; j < 8; j++) {
            float tv0 = u1s[(2 * h + 0) * 1152 + a * 72 + j * 8 + k];
            float tv1 = u1s[(2 * h + 1) * 1152 + a * 72 + j * 8 + k];
            uint64_t tb0 = pk2(tv0, tv0), tb1 = pk2(tv1, tv1);
            const uint64_t* fp = (const uint64_t*)(f1t + j * 16);
#pragma unroll
            for (int bp = 0; bp < 8; bp++) {
                uint64_t fv = fp[bp];
                ffma2(acc2[0][bp], tb0, fv);
                ffma2(acc2[1][bp], tb1, fv);
            }
        }
#pragma unroll
        for (int z = 0; z < 2; z++)
#pragma unroll
            for (int bp = 0; bp < 8; bp++) {
                float lo, hi;
                upk2(lo, hi, acc2[z][bp]);
                u2s[(2 * h + z) * 2176 + a * 136 + (2 * bp) * 8 + k] = lo;
                u2s[(2 * h + z) * 2176 + a * 136 + (2 * bp + 1) * 8 + k] = hi;
            }
    }
    __syncthreads();

    // ---- phase 3: acc2[s][cp2] packs (c4 = 2cp2, 2cp2+1) ----
    {
        int q = t & 3, ab0 = t >> 2;
#pragma unroll
        for (int r = 0; r < 4; r++) {
            int ab = ab0 + 64 * r;
            int a = ab >> 4, b = ab & 15;
            uint64_t acc2[4][2];
#pragma unroll
            for (int s = 0; s < 4; s++) { acc2[s][0] = 0ULL; acc2[s][1] = 0ULL; }
#pragma unroll
            for (int k = 0; k < 8; k++) {
                uint64_t tb[4];
#pragma unroll
                for (int s = 0; s < 4; s++) {
                    float tv = u2s[s * 2176 + a * 136 + b * 8 + k];
                    tb[s] = pk2(tv, tv);
                }
                const uint64_t* fp = (const uint64_t*)(f2t + k * 16 + q * 4);
                uint64_t f0p = fp[0], f1p = fp[1];
#pragma unroll
                for (int s = 0; s < 4; s++) {
                    ffma2(acc2[s][0], tb[s], f0p);
                    ffma2(acc2[s][1], tb[s], f1p);
                }
            }
            float4 bv = *(const float4*)&bias[ab * 16 + q * 4];
#pragma unroll
            for (int s = 0; s < 4; s++) {
                float c0, c1, c2, c3;
                upk2(c0, c1, acc2[s][0]);
                upk2(c2, c3, acc2[s][1]);
                float4 o = make_float4(c0 + bv.x, c1 + bv.y, c2 + bv.z, c3 + bv.w);
                *(float4*)&y[(s0 + s) * 4096 + ab * 16 + q * 4] = o;
            }
        }
    }
}

// ---------------- launch ----------------
extern "C" void kernel_launch(void* const* d_in, const int* in_sizes, int n_in,
                              void* d_out, int out_size) {
    const float* x    = (const float*)d_in[0];
    const float* core = (const float*)d_in[1];
    const float* f0   = (const float*)d_in[2];
    const float* f1   = (const float*)d_in[3];
    const float* f2   = (const float*)d_in[4];
    const float* f3   = (const float*)d_in[5];
    const float* f4   = (const float*)d_in[6];
    const float* f5   = (const float*)d_in[7];
    const float* bias = (const float*)d_in[8];
    float* y = (float*)d_out;

    int N = in_sizes[0] / 4096;

    const int SMEM_C = (4 * 1152 + 4 * 2176 + 384) * 4;   // 54784

    cudaFuncSetAttribute(k_stageA, cudaFuncAttributeMaxDynamicSharedMemorySize, SMEM_A);
    cudaFuncSetAttribute(k_gemm_mma, cudaFuncAttributeMaxDynamicSharedMemorySize, GEMM_SMEM);
    cudaFuncSetAttribute(k_stageC, cudaFuncAttributeMaxDynamicSharedMemorySize, SMEM_C);

    k_stageA<<<N / 2, 128, SMEM_A>>>(x, f3, f4, f5, core);
    k_gemm_mma<<<dim3(N / 128, 4), 512, GEMM_SMEM>>>();
    k_stageC<<<N / 4, 256, SMEM_C>>>(f0, f1, f2, bias, y);
}

// round 16
// speedup vs baseline: 1.0333x; 1.0333x over previous
#include <cuda_runtime.h>
#include <cuda_fp16.h>
#include <cstdint>

// ---------------- static device scratch (no allocations allowed) ----------------
__device__ __half g_T3h[4096 * 512];    // 4 MB : in-contracted activations (fp16)
__device__ float  g_U  [4096 * 512];    // 8 MB : core-contracted activations (fp32)
__device__ __half g_coreH[512 * 512];   // 0.5 MB : core pre-converted to fp16

__device__ __forceinline__ uint32_t smem_u32(const void* p) {
    uint32_t a;
    asm("{ .reg .u64 t; cvta.to.shared.u64 t, %1; cvt.u32.u64 %0, t; }" : "=r"(a) : "l"(p));
    return a;
}
__device__ __forceinline__ uint32_t pack_h2(float a, float b) {
    __half2 h = __floats2half2_rn(a, b);
    return *(uint32_t*)&h;
}
#define CP_ASYNC16(dst, src) \
    asm volatile("cp.async.cg.shared.global [%0], [%1], 16;" :: "r"(dst), "l"(src) : "memory")
#define CP_COMMIT() asm volatile("cp.async.commit_group;" ::: "memory")
#define CP_WAIT(n)  asm volatile("cp.async.wait_group %0;" :: "n"(n) : "memory")
#define LDMATRIX_X4(r0, r1, r2, r3, addr) \
    asm volatile("ldmatrix.sync.aligned.m8n8.x4.shared.b16 {%0,%1,%2,%3}, [%4];" \
        : "=r"(r0), "=r"(r1), "=r"(r2), "=r"(r3) : "r"(addr))

// ---------------- K1: stage A — 2 warps/sample, t2 overlays t1, fp16 output (R14) ----------------
static constexpr int T1L = 272;
static constexpr int SAMP = 8 * T1L;                        // 2176 floats / sample
static constexpr int SMEM_A = (2 * SAMP + 384) * 4;         // 18944 B

__global__ __launch_bounds__(128, 8) void k_stageA(const float* __restrict__ x,
                                                   const float* __restrict__ f3,
                                                   const float* __restrict__ f4,
                                                   const float* __restrict__ f5,
                                                   const float* __restrict__ core) {
    extern __shared__ float sm[];
    float* f3s = sm + 2 * SAMP;
    float* f4s = f3s + 128;
    float* f5s = f4s + 128;

    int t = threadIdx.x, wid = t >> 5, lane = t & 31;
    int sid = wid >> 1, half = wid & 1;

    if (t < 32) {
        int i = (blockIdx.x * 32 + t) * 4;
        float4 v = *(const float4*)(core + i);
        uint2 o = make_uint2(pack_h2(v.x, v.y), pack_h2(v.z, v.w));
        *(uint2*)(g_coreH + i) = o;
    }
    f3s[t] = f3[t]; f4s[t] = f4[t]; f5s[t] = f5[t];
    __syncthreads();

    float* t1s = sm + sid * SAMP;
    long s = (long)blockIdx.x * 2 + sid;
    const float* xs = x + s * 4096 + half * 128 + 4 * lane;

    // ---- phase 1 ----
    {
        float acc[4][8];
#pragma unroll
        for (int q = 0; q < 4; q++)
#pragma unroll
            for (int l = 0; l < 8; l++) acc[q][l] = 0.f;
#pragma unroll 4
        for (int d = 0; d < 16; d++) {
            float4 xv = *(const float4*)(xs + d * 256);
            float4 fA = *(const float4*)(f3s + d * 8);
            float4 fB = *(const float4*)(f3s + d * 8 + 4);
            float fl[8] = { fA.x, fA.y, fA.z, fA.w, fB.x, fB.y, fB.z, fB.w };
#pragma unroll
            for (int l = 0; l < 8; l++) {
                acc[0][l] += xv.x * fl[l]; acc[1][l] += xv.y * fl[l];
                acc[2][l] += xv.z * fl[l]; acc[3][l] += xv.w * fl[l];
            }
        }
#pragma unroll
        for (int l = 0; l < 8; l++) {
            float4 v = make_float4(acc[0][l], acc[1][l], acc[2][l], acc[3][l]);
            *(float4*)(t1s + l * T1L + half * 128 + 4 * lane) = v;
        }
    }
    __syncthreads();

    // ---- phase 2 (t2 overlays t1 after reads drain) ----
    {
        float acc[2][8];
#pragma unroll
        for (int z = 0; z < 2; z++)
#pragma unroll
            for (int m = 0; m < 8; m++) acc[z][m] = 0.f;
#pragma unroll
        for (int e = 0; e < 16; e++) {
            float tv[2];
#pragma unroll
            for (int z = 0; z < 2; z++) {
                int p = half * 64 + 32 * z + lane, l = p >> 4, f = p & 15;
                tv[z] = t1s[l * T1L + e * 16 + f];
            }
            float4 fA = *(const float4*)(f4s + e * 8);
            float4 fB = *(const float4*)(f4s + e * 8 + 4);
            float fm[8] = { fA.x, fA.y, fA.z, fA.w, fB.x, fB.y, fB.z, fB.w };
#pragma unroll
            for (int m = 0; m < 8; m++)
#pragma unroll
                for (int z = 0; z < 2; z++) acc[z][m] += tv[z] * fm[m];
        }
        __syncthreads();
#pragma unroll
        for (int z = 0; z < 2; z++) {
            int p = half * 64 + 32 * z + lane, l = p >> 4, f = p & 15;
#pragma unroll
            for (int m = 0; m < 8; m++)
                t1s[l * 144 + m * 17 + f] = acc[z][m];
        }
    }
    __syncthreads();

    // ---- phase 3 -> g_T3h (fp16) ----
    {
        int lm = half * 32 + lane, l = lm >> 3, m = lm & 7;
        float acc[8];
#pragma unroll
        for (int n = 0; n < 8; n++) acc[n] = 0.f;
#pragma unroll
        for (int f = 0; f < 16; f++) {
            float tv = t1s[l * 144 + m * 17 + f];
            float4 fA = *(const float4*)(f5s + f * 8);
            float4 fB = *(const float4*)(f5s + f * 8 + 4);
            float fn[8] = { fA.x, fA.y, fA.z, fA.w, fB.x, fB.y, fB.z, fB.w };
#pragma unroll
            for (int n = 0; n < 8; n++) acc[n] += tv * fn[n];
        }
        uint4 o = make_uint4(pack_h2(acc[0], acc[1]), pack_h2(acc[2], acc[3]),
                             pack_h2(acc[4], acc[5]), pack_h2(acc[6], acc[7]));
        *(uint4*)(g_T3h + s * 512 + lm * 8) = o;
    }
}

// ---------------- K2: stage B via mma.sync fp16 + ldmatrix, 512 threads, 3-stage ----------------
static constexpr int GS = 36;                         // words per row
static constexpr int OP_ST = 128 * GS;                // words per operand stage
static constexpr int GEMM_SMEM = 6 * OP_ST * 4;       // 110592 B

__global__ __launch_bounds__(512) void k_gemm_mma() {
    extern __shared__ float sm[];
    uint32_t sm_u = smem_u32(sm);

    int t = threadIdx.x;
    int lane = t & 31, wid = t >> 5;
    int warp_m = (wid & 3) * 32;
    int warp_n = (wid >> 2) * 32;
    long s0 = (long)blockIdx.x * 128;
    int n0 = blockIdx.y * 128;

    // cp.async load mapping (2 x 16B per thread per operand per chunk)
    int rr[2], sg[2];
#pragma unroll
    for (int i = 0; i < 2; i++) {
        int ii = t + 512 * i;
        rr[i] = ii >> 3;
        sg[i] = ii & 7;
    }
    const __half* AGp[2]; const __half* BGp[2]; uint32_t Sd[2];
#pragma unroll
    for (int i = 0; i < 2; i++) {
        AGp[i] = g_T3h + (s0 + rr[i]) * 512 + sg[i] * 8;
        BGp[i] = g_coreH + (size_t)(n0 + rr[i]) * 512 + sg[i] * 8;
        Sd[i] = (uint32_t)((rr[i] * GS + sg[i] * 4) * 4);
    }

    // ldmatrix per-lane byte offsets (within an operand stage)
    // A (mt): row = warp_m + mt*16 + (lane&15); k-half-block = (lane>>4)&1 (4 words)
    uint32_t aOff[2];
#pragma unroll
    for (int mt = 0; mt < 2; mt++)
        aOff[mt] = (uint32_t)(((warp_m + mt * 16 + (lane & 15)) * GS
                              + ((lane >> 4) & 1) * 4) * 4);
    // B (pair p -> nt = 2p + ((lane>>4)&1)): row = warp_n + nt*8 + (lane&7);
    // k-half-block = (lane>>3)&1
    uint32_t bOff[2];
#pragma unroll
    for (int p = 0; p < 2; p++)
        bOff[p] = (uint32_t)(((warp_n + (2 * p + ((lane >> 4) & 1)) * 8 + (lane & 7)) * GS
                             + ((lane >> 3) & 1) * 4) * 4);

    float acc[2][4][4];
#pragma unroll
    for (int mt = 0; mt < 2; mt++)
#pragma unroll
        for (int nt = 0; nt < 4; nt++)
#pragma unroll
            for (int i = 0; i < 4; i++) acc[mt][nt][i] = 0.f;

    int fr = lane >> 2;

    // prologue: issue chunks 0,1
#pragma unroll
    for (int pc = 0; pc < 2; pc++) {
        uint32_t Au = sm_u + (2 * pc) * OP_ST * 4;
        uint32_t Bu = sm_u + (2 * pc + 1) * OP_ST * 4;
#pragma unroll
        for (int i = 0; i < 2; i++) {
            CP_ASYNC16(Au + Sd[i], AGp[i] + pc * 64);
            CP_ASYNC16(Bu + Sd[i], BGp[i] + pc * 64);
        }
        CP_COMMIT();
    }

#pragma unroll 1
    for (int c = 0; c < 8; c++) {
        int p = c % 3;
        if (c == 7) { CP_WAIT(0); } else { CP_WAIT(1); }
        __syncthreads();

        uint32_t Abase = sm_u + (2 * p) * OP_ST * 4;
        uint32_t Bbase = sm_u + (2 * p + 1) * OP_ST * 4;
#pragma unroll
        for (int ks = 0; ks < 4; ks++) {
            uint32_t kb = (uint32_t)(ks * 8 * 4);   // 16 halfs per ks = 8 words
            uint32_t a[2][4], b[4][2];
#pragma unroll
            for (int mt = 0; mt < 2; mt++)
                LDMATRIX_X4(a[mt][0], a[mt][1], a[mt][2], a[mt][3],
                            Abase + aOff[mt] + kb);
#pragma unroll
            for (int bp = 0; bp < 2; bp++)
                LDMATRIX_X4(b[2 * bp][0], b[2 * bp][1], b[2 * bp + 1][0], b[2 * bp + 1][1],
                            Bbase + bOff[bp] + kb);
#pragma unroll
            for (int mt = 0; mt < 2; mt++)
#pragma unroll
                for (int nt = 0; nt < 4; nt++)
                    asm volatile(
                        "mma.sync.aligned.m16n8k16.row.col.f32.f16.f16.f32 "
                        "{%0,%1,%2,%3}, {%4,%5,%6,%7}, {%8,%9}, {%0,%1,%2,%3};"
                        : "+f"(acc[mt][nt][0]), "+f"(acc[mt][nt][1]),
                          "+f"(acc[mt][nt][2]), "+f"(acc[mt][nt][3])
                        : "r"(a[mt][0]), "r"(a[mt][1]), "r"(a[mt][2]), "r"(a[mt][3]),
                          "r"(b[nt][0]), "r"(b[nt][1]));
        }

        if (c + 2 < 8) {
            int pn = (c + 2) % 3;
            uint32_t Au = sm_u + (2 * pn) * OP_ST * 4;
            uint32_t Bu = sm_u + (2 * pn + 1) * OP_ST * 4;
            int off = (c + 2) * 64;
#pragma unroll
            for (int i = 0; i < 2; i++) {
                CP_ASYNC16(Au + Sd[i], AGp[i] + off);
                CP_ASYNC16(Bu + Sd[i], BGp[i] + off);
            }
            CP_COMMIT();
        }
    }

    // epilogue (fp32 accumulators)
    int cp = (lane & 3) * 2;
#pragma unroll
    for (int mt = 0; mt < 2; mt++)
#pragma unroll
        for (int h = 0; h < 2; h++) {
            long m = s0 + warp_m + mt * 16 + fr + h * 8;
            float* dst = g_U + m * 512 + n0 + warp_n + cp;
#pragma unroll
            for (int nt = 0; nt < 4; nt++) {
                float2 v = make_float2(acc[mt][nt][h * 2], acc[mt][nt][h * 2 + 1]);
                *(float2*)(dst + nt * 8) = v;
            }
        }
}

// ---------------- K3: stage C (block version, transposed factors for LDS.128, R14) ----------------
__global__ __launch_bounds__(256, 3) void k_stageC(const float* __restrict__ f0,
                                                   const float* __restrict__ f1,
                                                   const float* __restrict__ f2,
                                                   const float* __restrict__ bias,
                                                   float* __restrict__ y) {
    extern __shared__ float sm[];
    float* u1s = sm;                    // 4 * 1152
    float* u2s = sm + 4 * 1152;         // 4 * 2176
    float* f0t = u2s + 4 * 2176;
    float* f1t = f0t + 128;
    float* f2t = f1t + 128;

    int t = threadIdx.x;
    if (t < 128) {
        int rr = t >> 3, cc = t & 7;
        f0t[cc * 16 + rr] = f0[t];
        f1t[cc * 16 + rr] = f1[t];
        f2t[cc * 16 + rr] = f2[t];
    }
    __syncthreads();

    long s0 = (long)blockIdx.x * 4;

    {
        int g = t >> 6, jk = t & 63;
        float acc[4][4];
#pragma unroll
        for (int s = 0; s < 4; s++)
#pragma unroll
            for (int a4 = 0; a4 < 4; a4++) acc[s][a4] = 0.f;
#pragma unroll
        for (int i = 0; i < 8; i++) {
            float uv0 = g_U[(s0 + 0) * 512 + i * 64 + jk];
            float uv1 = g_U[(s0 + 1) * 512 + i * 64 + jk];
            float uv2 = g_U[(s0 + 2) * 512 + i * 64 + jk];
            float uv3 = g_U[(s0 + 3) * 512 + i * 64 + jk];
            float4 fv = *(const float4*)(f0t + i * 16 + g * 4);
            float fa[4] = { fv.x, fv.y, fv.z, fv.w };
#pragma unroll
            for (int a4 = 0; a4 < 4; a4++) {
                acc[0][a4] += uv0 * fa[a4]; acc[1][a4] += uv1 * fa[a4];
                acc[2][a4] += uv2 * fa[a4]; acc[3][a4] += uv3 * fa[a4];
            }
        }
#pragma unroll
        for (int s = 0; s < 4; s++)
#pragma unroll
            for (int a4 = 0; a4 < 4; a4++)
                u1s[s * 1152 + (g * 4 + a4) * 72 + jk] = acc[s][a4];
    }
    __syncthreads();

    {
        int h = t >> 7, pair = t & 127;
        int a = pair >> 3, k = pair & 7;
        float acc[2][16];
#pragma unroll
        for (int z = 0; z < 2; z++)
#pragma unroll
            for (int b = 0; b < 16; b++) acc[z][b] = 0.f;
#pragma unroll
        for (int j = 0; j < 8; j++) {
            float tv0 = u1s[(2 * h + 0) * 1152 + a * 72 + j * 8 + k];
            float tv1 = u1s[(2 * h + 1) * 1152 + a * 72 + j * 8 + k];
            float4 g0 = *(const float4*)(f1t + j * 16);
            float4 g1 = *(const float4*)(f1t + j * 16 + 4);
            float4 g2 = *(const float4*)(f1t + j * 16 + 8);
            float4 g3 = *(const float4*)(f1t + j * 16 + 12);
            float fb[16] = { g0.x, g0.y, g0.z, g0.w, g1.x, g1.y, g1.z, g1.w,
                             g2.x, g2.y, g2.z, g2.w, g3.x, g3.y, g3.z, g3.w };
#pragma unroll
            for (int b = 0; b < 16; b++) {
                acc[0][b] += tv0 * fb[b]; acc[1][b] += tv1 * fb[b];
            }
        }
#pragma unroll
        for (int z = 0; z < 2; z++)
#pragma unroll
            for (int b = 0; b < 16; b++)
                u2s[(2 * h + z) * 2176 + a * 136 + b * 8 + k] = acc[z][b];
    }
    __syncthreads();

    {
        int q = t & 3, ab0 = t >> 2;
#pragma unroll
        for (int r = 0; r < 4; r++) {
            int ab = ab0 + 64 * r;
            int a = ab >> 4, b = ab & 15;
            float acc[4][4];
#pragma unroll
            for (int s = 0; s < 4; s++)
#pragma unroll
                for (int c4 = 0; c4 < 4; c4++) acc[s][c4] = 0.f;
#pragma unroll
            for (int k = 0; k < 8; k++) {
                float tv0 = u2s[0 * 2176 + a * 136 + b * 8 + k];
                float tv1 = u2s[1 * 2176 + a * 136 + b * 8 + k];
                float tv2 = u2s[2 * 2176 + a * 136 + b * 8 + k];
                float tv3 = u2s[3 * 2176 + a * 136 + b * 8 + k];
                float4 fv = *(const float4*)(f2t + k * 16 + q * 4);
                float fcv[4] = { fv.x, fv.y, fv.z, fv.w };
#pragma unroll
                for (int c4 = 0; c4 < 4; c4++) {
                    acc[0][c4] += tv0 * fcv[c4]; acc[1][c4] += tv1 * fcv[c4];
                    acc[2][c4] += tv2 * fcv[c4]; acc[3][c4] += tv3 * fcv[c4];
                }
            }
            float4 bv = *(const float4*)&bias[ab * 16 + q * 4];
#pragma unroll
            for (int s = 0; s < 4; s++) {
                float4 o = make_float4(acc[s][0] + bv.x, acc[s][1] + bv.y,
                                       acc[s][2] + bv.z, acc[s][3] + bv.w);
                *(float4*)&y[(s0 + s) * 4096 + ab * 16 + q * 4] = o;
            }
        }
    }
}

// ---------------- launch ----------------
extern "C" void kernel_launch(void* const* d_in, const int* in_sizes, int n_in,
                              void* d_out, int out_size) {
    const float* x    = (const float*)d_in[0];
    const float* core = (const float*)d_in[1];
    const float* f0   = (const float*)d_in[2];
    const float* f1   = (const float*)d_in[3];
    const float* f2   = (const float*)d_in[4];
    const float* f3   = (const float*)d_in[5];
    const float* f4   = (const float*)d_in[6];
    const float* f5   = (const float*)d_in[7];
    const float* bias = (const float*)d_in[8];
    float* y = (float*)d_out;

    int N = in_sizes[0] / 4096;

    const int SMEM_C = (4 * 1152 + 4 * 2176 + 384) * 4;   // 54784

    cudaFuncSetAttribute(k_stageA, cudaFuncAttributeMaxDynamicSharedMemorySize, SMEM_A);
    cudaFuncSetAttribute(k_gemm_mma, cudaFuncAttributeMaxDynamicSharedMemorySize, GEMM_SMEM);
    cudaFuncSetAttribute(k_stageC, cudaFuncAttributeMaxDynamicSharedMemorySize, SMEM_C);

    k_stageA<<<N / 2, 128, SMEM_A>>>(x, f3, f4, f5, core);
    k_gemm_mma<<<dim3(N / 128, 4), 512, GEMM_SMEM>>>();
    k_stageC<<<N / 4, 256, SMEM_C>>>(f0, f1, f2, bias, y);
}